// round 3
// baseline (speedup 1.0000x reference)
#include <cuda_runtime.h>

#define NN 200000
#define NE 6400000
#define NG 1024
#define NEMB 1032
#define TPB 256
#define NBB ((NN + TPB - 1) / TPB)           // 782 node blocks
#define NB_EDGE2 ((NE / 2 + TPB - 1) / TPB)  // 12500 (2 edges/thread, exact)
#define NBG (NN / 8)                         // 25000 gather blocks/graph (8 warps = 8 nodes)

// Scratch (device globals; allocation-free)
__device__ int    g_degi[2][NN];       // in-degree (int)
__device__ int    g_off[2][NN];        // CSR offsets
__device__ int    g_cur[2][NN];        // scatter cursors
__device__ int    g_srcs[2][NE];       // CSR: src ids grouped by dst
__device__ float2 g_rec[2][NN];        // {id bits, dis}
__device__ float4 g_hs[2][NN * 4];     // layer-2 scaled features
__device__ float4 g_tab[NEMB * 4];     // emb @ W1 (66KB, L1-hot)
__device__ float4 g_pool[2 * NG * 4];  // pooled sums
__device__ float  g_cnt[2 * NG];       // nodes per graph
__device__ int    g_bsum[2 * NBB];     // block degree sums
__device__ int    g_bexcl[2 * NBB];    // exclusive block prefix

__device__ __forceinline__ void red_add_v4(float4* addr, float4 v) {
    asm volatile("red.global.add.v4.f32 [%0], {%1,%2,%3,%4};"
                 :: "l"(addr), "f"(v.x), "f"(v.y), "f"(v.z), "f"(v.w)
                 : "memory");
}

// tab = emb @ W1
__global__ void k_tab(const float* __restrict__ emb, const float* __restrict__ W1) {
    __shared__ float Ws[256];
    if (threadIdx.x < 256) Ws[threadIdx.x] = W1[threadIdx.x];
    __syncthreads();
    int r = blockIdx.x * blockDim.x + threadIdx.x;
    if (r >= NEMB) return;
    const float* x = emb + r * 16;
    float acc[16];
#pragma unroll
    for (int j = 0; j < 16; j++) acc[j] = 0.f;
#pragma unroll
    for (int k = 0; k < 16; k++) {
        float xk = __ldg(x + k);
#pragma unroll
        for (int j = 0; j < 16; j++) acc[j] += xk * Ws[k * 16 + j];
    }
    float4* o = g_tab + r * 4;
#pragma unroll
    for (int c = 0; c < 4; c++)
        o[c] = make_float4(acc[4*c], acc[4*c+1], acc[4*c+2], acc[4*c+3]);
}

__global__ void k_zero() {
    int i = blockIdx.x * blockDim.x + threadIdx.x;
    if (i < NN) { g_degi[0][i] = 0; g_degi[1][i] = 0; }
    if (i < 2 * NG * 4) g_pool[i] = make_float4(0.f, 0.f, 0.f, 0.f);
    if (i < 2 * NG) g_cnt[i] = 0.f;
}

// In-degree count (int atomics), both graphs, 2 edges/thread
__global__ void k_count(const int* __restrict__ ei0, const int* __restrict__ ei1) {
    int g = blockIdx.x >= NB_EDGE2 ? 1 : 0;
    const int* dst = (g ? ei1 : ei0) + NE;
    int i = (blockIdx.x - g * NB_EDGE2) * blockDim.x + threadIdx.x;
    int2 d = __ldg((const int2*)dst + i);
    atomicAdd(&g_degi[g][d.x], 1);
    atomicAdd(&g_degi[g][d.y], 1);
}

// Block-level degree sums
__global__ void k_psum1() {
    int g = blockIdx.x >= NBB ? 1 : 0;
    int blk = blockIdx.x - g * NBB;
    int i = blk * TPB + threadIdx.x;
    __shared__ int s[TPB];
    int v = (i < NN) ? g_degi[g][i] : 0;
    s[threadIdx.x] = v;
    __syncthreads();
#pragma unroll
    for (int d = TPB / 2; d > 0; d >>= 1) {
        if (threadIdx.x < d) s[threadIdx.x] += s[threadIdx.x + d];
        __syncthreads();
    }
    if (threadIdx.x == 0) g_bsum[g * NBB + blk] = s[0];
}

// Scan block sums (one block per graph)
__global__ void k_psum2() {
    int g = blockIdx.x;
    int t = threadIdx.x;
    __shared__ int s[1024];
    int v = (t < NBB) ? g_bsum[g * NBB + t] : 0;
    s[t] = v;
    __syncthreads();
#pragma unroll
    for (int d = 1; d < 1024; d <<= 1) {
        int x = (t >= d) ? s[t - d] : 0;
        __syncthreads();
        s[t] += x;
        __syncthreads();
    }
    if (t < NBB) g_bexcl[g * NBB + t] = t ? s[t - 1] : 0;
}

// Per-node offsets + cursors + rec{id,dis} + graph node counts
__global__ void k_psum3(const int* __restrict__ ids0, const int* __restrict__ ids1,
                        const int* __restrict__ b0, const int* __restrict__ b1) {
    int g = blockIdx.x >= NBB ? 1 : 0;
    int blk = blockIdx.x - g * NBB;
    int i = blk * TPB + threadIdx.x;
    int t = threadIdx.x;
    __shared__ int s[TPB];
    int deg = (i < NN) ? g_degi[g][i] : 0;
    s[t] = deg;
    __syncthreads();
#pragma unroll
    for (int d = 1; d < TPB; d <<= 1) {
        int x = (t >= d) ? s[t - d] : 0;
        __syncthreads();
        s[t] += x;
        __syncthreads();
    }
    if (i >= NN) return;
    int off = g_bexcl[g * NBB + blk] + s[t] - deg;
    g_off[g][i] = off;
    g_cur[g][i] = off;
    float2 r;
    r.x = __int_as_float(__ldg((g ? ids1 : ids0) + i));
    r.y = rsqrtf((float)deg + 1.0f);
    g_rec[g][i] = r;
    atomicAdd(&g_cnt[g * NG + __ldg((g ? b1 : b0) + i)], 1.0f);
}

// Scatter src ids into CSR slots
__global__ void k_scatter(const int* __restrict__ ei0, const int* __restrict__ ei1) {
    int g = blockIdx.x >= NB_EDGE2 ? 1 : 0;
    const int* ei = g ? ei1 : ei0;
    int i = (blockIdx.x - g * NB_EDGE2) * blockDim.x + threadIdx.x;
    int2 s = __ldg((const int2*)ei + i);
    int2 d = __ldg((const int2*)(ei + NE) + i);
    int slot0 = atomicAdd(&g_cur[g][d.x], 1);
    g_srcs[g][slot0] = s.x;
    int slot1 = atomicAdd(&g_cur[g][d.y], 1);
    g_srcs[g][slot1] = s.y;
}

// Layer-1: warp-per-node gather of tab[id_s]*dis_s, fused relu+matvec epilogue
// lanes: eslot = lane>>2 (8 edge slots), c = lane&3 (feature quad)
__global__ void k_gather1(const float* __restrict__ W2, const float* __restrict__ b1p) {
    __shared__ float Ws[256];
    __shared__ float bs[16];
    if (threadIdx.x < 256) Ws[threadIdx.x] = W2[threadIdx.x];
    if (threadIdx.x < 16) bs[threadIdx.x] = b1p[threadIdx.x];
    __syncthreads();
    int g = blockIdx.x >= NBG ? 1 : 0;
    int node = (blockIdx.x - g * NBG) * 8 + (threadIdx.x >> 5);
    int lane = threadIdx.x & 31;
    int eslot = lane >> 2, c = lane & 3;
    int off = g_off[g][node];
    int deg = g_degi[g][node];
    const int* sp = g_srcs[g] + off;
    float4 acc = make_float4(0.f, 0.f, 0.f, 0.f);
    for (int e = eslot; e < deg; e += 8) {
        int sidx = __ldg(sp + e);
        float2 r = __ldg(&g_rec[g][sidx]);
        float4 tv = __ldg(&g_tab[(size_t)__float_as_int(r.x) * 4 + c]);
        acc.x += tv.x * r.y; acc.y += tv.y * r.y;
        acc.z += tv.z * r.y; acc.w += tv.w * r.y;
    }
#pragma unroll
    for (int st = 4; st < 32; st <<= 1) {
        acc.x += __shfl_xor_sync(0xffffffffu, acc.x, st);
        acc.y += __shfl_xor_sync(0xffffffffu, acc.y, st);
        acc.z += __shfl_xor_sync(0xffffffffu, acc.z, st);
        acc.w += __shfl_xor_sync(0xffffffffu, acc.w, st);
    }
    // epilogue: every lane has full t_c for its c
    float2 rr = g_rec[g][node];
    float d = rr.y;
    int id = __float_as_int(rr.x);
    float4 tv = __ldg(&g_tab[(size_t)id * 4 + c]);
    float y[4];
    y[0] = fmaxf(d * (acc.x + tv.x * d) + bs[4*c+0], 0.f);
    y[1] = fmaxf(d * (acc.y + tv.y * d) + bs[4*c+1], 0.f);
    y[2] = fmaxf(d * (acc.z + tv.z * d) + bs[4*c+2], 0.f);
    y[3] = fmaxf(d * (acc.w + tv.w * d) + bs[4*c+3], 0.f);
    // matvec partials: lane c owns k in [4c, 4c+4)
    float p[16];
#pragma unroll
    for (int j = 0; j < 16; j++) p[j] = 0.f;
#pragma unroll
    for (int kk = 0; kk < 4; kk++) {
        float yk = y[kk];
        int k = 4 * c + kk;
#pragma unroll
        for (int j = 0; j < 16; j++) p[j] += yk * Ws[k * 16 + j];
    }
#pragma unroll
    for (int st = 1; st < 4; st <<= 1) {
#pragma unroll
        for (int j = 0; j < 16; j++)
            p[j] += __shfl_xor_sync(0xffffffffu, p[j], st);
    }
    if (lane < 4)
        g_hs[g][(size_t)node * 4 + lane] =
            make_float4(p[4*lane] * d, p[4*lane+1] * d, p[4*lane+2] * d, p[4*lane+3] * d);
}

// Layer-2: warp-per-node gather of hs2[src], fused epilogue + pool red
__global__ void k_gather2(const float* __restrict__ b2p,
                          const int* __restrict__ b0, const int* __restrict__ b1) {
    __shared__ float bs[16];
    if (threadIdx.x < 16) bs[threadIdx.x] = b2p[threadIdx.x];
    __syncthreads();
    int g = blockIdx.x >= NBG ? 1 : 0;
    int node = (blockIdx.x - g * NBG) * 8 + (threadIdx.x >> 5);
    int lane = threadIdx.x & 31;
    int eslot = lane >> 2, c = lane & 3;
    int off = g_off[g][node];
    int deg = g_degi[g][node];
    const int* sp = g_srcs[g] + off;
    float4 acc = make_float4(0.f, 0.f, 0.f, 0.f);
    for (int e = eslot; e < deg; e += 8) {
        int sidx = __ldg(sp + e);
        float4 v = __ldg(&g_hs[g][(size_t)sidx * 4 + c]);
        acc.x += v.x; acc.y += v.y; acc.z += v.z; acc.w += v.w;
    }
#pragma unroll
    for (int st = 4; st < 32; st <<= 1) {
        acc.x += __shfl_xor_sync(0xffffffffu, acc.x, st);
        acc.y += __shfl_xor_sync(0xffffffffu, acc.y, st);
        acc.z += __shfl_xor_sync(0xffffffffu, acc.z, st);
        acc.w += __shfl_xor_sync(0xffffffffu, acc.w, st);
    }
    if (lane < 4) {
        float d = g_rec[g][node].y;
        float4 h = g_hs[g][(size_t)node * 4 + lane];
        float4 o;
        o.x = d * (acc.x + h.x) + bs[4*lane+0];
        o.y = d * (acc.y + h.y) + bs[4*lane+1];
        o.z = d * (acc.z + h.z) + bs[4*lane+2];
        o.w = d * (acc.w + h.w) + bs[4*lane+3];
        int gr = __ldg((g ? b1 : b0) + node);
        red_add_v4(&g_pool[((size_t)(g * NG + gr)) * 4 + lane], o);
    }
}

// Mean pool + concat + FC head
__global__ void k_final(const float* __restrict__ fcW, const float* __restrict__ fcb,
                        float* __restrict__ out) {
    int b = blockIdx.x * blockDim.x + threadIdx.x;
    if (b >= NG) return;
    float inv_r = 1.0f / fmaxf(g_cnt[b], 1.0f);
    float inv_l = 1.0f / fmaxf(g_cnt[NG + b], 1.0f);
    const float4* pr = g_pool + (size_t)b * 4;
    const float4* pl = g_pool + (size_t)(NG + b) * 4;
    float v[32];
#pragma unroll
    for (int c = 0; c < 4; c++) {
        float4 r = pr[c];
        v[4*c+0] = r.x * inv_r; v[4*c+1] = r.y * inv_r;
        v[4*c+2] = r.z * inv_r; v[4*c+3] = r.w * inv_r;
        float4 l = pl[c];
        v[16+4*c+0] = l.x * inv_l; v[16+4*c+1] = l.y * inv_l;
        v[16+4*c+2] = l.z * inv_l; v[16+4*c+3] = l.w * inv_l;
    }
#pragma unroll
    for (int o = 0; o < 6; o++) {
        float s = __ldg(fcb + o);
#pragma unroll
        for (int j = 0; j < 32; j++) s += v[j] * __ldg(fcW + o * 32 + j);
        if (o < 3) out[b * 3 + o] = s;
        else       out[NG * 3 + b * 3 + (o - 3)] = s;
    }
}

extern "C" void kernel_launch(void* const* d_in, const int* in_sizes, int n_in,
                              void* d_out, int out_size) {
    const float* emb = (const float*)d_in[0];
    const float* W1  = (const float*)d_in[1];
    const float* b1  = (const float*)d_in[2];
    const float* W2  = (const float*)d_in[3];
    const float* b2  = (const float*)d_in[4];
    const float* fcW = (const float*)d_in[5];
    const float* fcb = (const float*)d_in[6];
    const int* ids0  = (const int*)d_in[7];
    const int* ei0   = (const int*)d_in[8];
    const int* b0    = (const int*)d_in[9];
    const int* ids1  = (const int*)d_in[10];
    const int* ei1   = (const int*)d_in[11];
    const int* b1i   = (const int*)d_in[12];
    float* out = (float*)d_out;

    k_tab    <<<(NEMB + TPB - 1) / TPB, TPB>>>(emb, W1);
    k_zero   <<<(NN + TPB - 1) / TPB, TPB>>>();
    k_count  <<<2 * NB_EDGE2, TPB>>>(ei0, ei1);
    k_psum1  <<<2 * NBB, TPB>>>();
    k_psum2  <<<2, 1024>>>();
    k_psum3  <<<2 * NBB, TPB>>>(ids0, ids1, b0, b1i);
    k_scatter<<<2 * NB_EDGE2, TPB>>>(ei0, ei1);
    k_gather1<<<2 * NBG, TPB>>>(W2, b1);
    k_gather2<<<2 * NBG, TPB>>>(b2, b0, b1i);
    k_final  <<<(NG + TPB - 1) / TPB, TPB>>>(fcW, fcb, out);
}

// round 4
// speedup vs baseline: 1.4170x; 1.4170x over previous
#include <cuda_runtime.h>

#define NN 200000
#define NE 6400000
#define NG 1024
#define NEMB 1032
#define TPB 256
#define NREP 16
#define NBB ((NN + TPB - 1) / TPB)           // 782
#define NB_EDGE2 ((NE / 2 + TPB - 1) / TPB)  // 12500 (2 edges/thread, exact)

// Scratch (device globals; allocation-free)
__device__ float4 g_t[2][NN * 4];        // layer-1 accumulators (preloaded with self term)
__device__ float4 g_hs[2][NN * 4];       // hs1 = tab[id]*dis (gather source, layer 1)
__device__ float2 g_rec[2][NN];          // {dis, batch bits}
__device__ float4 g_w[2][NN * 2];        // projected layer-2 features: 6 floats / 32B slot
__device__ int    g_deg[2][NN];          // in-degree
__device__ float4 g_tab[NEMB * 4];       // emb @ W1 (66KB, L1-hot)
__device__ float4 g_pool6[2 * NREP * NG * 2];  // [g][rep][graph][8 floats]
__device__ float  g_cnt[2 * NG];
__device__ float  g_M[2][16][8];         // M_g = W2 @ P_g^T  (16x6, padded)
__device__ float  g_b2P[2][8];           // b2 @ P_g^T

__device__ __forceinline__ void red_add_v4(float* addr, float a, float b, float c, float d) {
    asm volatile("red.global.add.v4.f32 [%0], {%1,%2,%3,%4};"
                 :: "l"(addr), "f"(a), "f"(b), "f"(c), "f"(d) : "memory");
}
__device__ __forceinline__ void red_add_v2(float* addr, float a, float b) {
    asm volatile("red.global.add.v2.f32 [%0], {%1,%2};"
                 :: "l"(addr), "f"(a), "f"(b) : "memory");
}

// tab = emb @ W1
__global__ void k_tab(const float* __restrict__ emb, const float* __restrict__ W1) {
    __shared__ float Ws[256];
    if (threadIdx.x < 256) Ws[threadIdx.x] = W1[threadIdx.x];
    __syncthreads();
    int r = blockIdx.x * blockDim.x + threadIdx.x;
    if (r >= NEMB) return;
    const float* x = emb + r * 16;
    float acc[16];
#pragma unroll
    for (int j = 0; j < 16; j++) acc[j] = 0.f;
#pragma unroll
    for (int k = 0; k < 16; k++) {
        float xk = __ldg(x + k);
#pragma unroll
        for (int j = 0; j < 16; j++) acc[j] += xk * Ws[k * 16 + j];
    }
    float4* o = g_tab + r * 4;
#pragma unroll
    for (int c = 0; c < 4; c++)
        o[c] = make_float4(acc[4*c], acc[4*c+1], acc[4*c+2], acc[4*c+3]);
}

// M_g = W2 @ P_g^T ; b2P_g = b2 @ P_g^T   (P_g[o][j] = fcW[o*32 + 16g + j])
__global__ void k_mat(const float* __restrict__ W2, const float* __restrict__ b2,
                      const float* __restrict__ fcW) {
    int t = threadIdx.x;
    if (t < 192) {
        int g = t / 96, r = t % 96, k = r / 6, o = r % 6;
        float s = 0.f;
#pragma unroll
        for (int j = 0; j < 16; j++) s += __ldg(W2 + k * 16 + j) * __ldg(fcW + o * 32 + 16 * g + j);
        g_M[g][k][o] = s;
    } else if (t < 204) {
        int g = (t - 192) / 6, o = (t - 192) % 6;
        float s = 0.f;
#pragma unroll
        for (int j = 0; j < 16; j++) s += __ldg(b2 + j) * __ldg(fcW + o * 32 + 16 * g + j);
        g_b2P[g][o] = s;
    }
}

// Zero deg, pool6, cnt (t is preloaded by k_embed — no big zero pass)
__global__ void k_zero() {
    int i = blockIdx.x * blockDim.x + threadIdx.x;
    if (i < NN) { g_deg[0][i] = 0; g_deg[1][i] = 0; }
    if (i < 2 * NREP * NG * 2) g_pool6[i] = make_float4(0.f, 0.f, 0.f, 0.f);
    if (i < 2 * NG) g_cnt[i] = 0.f;
}

// In-degree count, both graphs, 2 edges/thread
__global__ void k_count(const int* __restrict__ ei0, const int* __restrict__ ei1) {
    int g = blockIdx.x >= NB_EDGE2 ? 1 : 0;
    const int* dst = (g ? ei1 : ei0) + NE;
    int i = (blockIdx.x - g * NB_EDGE2) * blockDim.x + threadIdx.x;
    int2 d = __ldg((const int2*)dst + i);
    atomicAdd(&g_deg[g][d.x], 1);
    atomicAdd(&g_deg[g][d.y], 1);
}

// dis; hs1 = tab[id]*dis written to BOTH g_hs (gather src) and g_t (self preload);
// rec = {dis, batch}; per-graph counts
__global__ void k_embed(const int* __restrict__ ids0, const int* __restrict__ ids1,
                        const int* __restrict__ b0, const int* __restrict__ b1) {
    int g = blockIdx.x >= NBB ? 1 : 0;
    int i = (blockIdx.x - g * NBB) * blockDim.x + threadIdx.x;
    if (i >= NN) return;
    float d = rsqrtf((float)g_deg[g][i] + 1.0f);
    int id = __ldg((g ? ids1 : ids0) + i);
    int bt = __ldg((g ? b1 : b0) + i);
    float2 r; r.x = d; r.y = __int_as_float(bt);
    g_rec[g][i] = r;
    const float4* tb = g_tab + (size_t)id * 4;
    float4* hp = g_hs[g] + (size_t)i * 4;
    float4* tp = g_t[g] + (size_t)i * 4;
#pragma unroll
    for (int c = 0; c < 4; c++) {
        float4 v = __ldg(tb + c);
        float4 hv = make_float4(v.x * d, v.y * d, v.z * d, v.w * d);
        hp[c] = hv;
        tp[c] = hv;
    }
    atomicAdd(&g_cnt[g * NG + bt], 1.0f);
}

// Layer-1 edge pass: t[dst] += hs1[src]  (fp32 v4 reds; the hot kernel)
__global__ void k_edge1(const int* __restrict__ ei0, const int* __restrict__ ei1) {
    int g = blockIdx.x >= NB_EDGE2 ? 1 : 0;
    const int* ei = g ? ei1 : ei0;
    int i = (blockIdx.x - g * NB_EDGE2) * blockDim.x + threadIdx.x;
    int2 s = __ldg((const int2*)ei + i);
    int2 d = __ldg((const int2*)(ei + NE) + i);
    const float4* hs = g_hs[g];
    float4* t = g_t[g];
#pragma unroll
    for (int k = 0; k < 2; k++) {
        int sv = k ? s.y : s.x;
        int dv = k ? d.y : d.x;
        const float4* hp = hs + (size_t)sv * 4;
        float* tp = (float*)(t + (size_t)dv * 4);
        float4 v0 = __ldg(hp + 0);
        float4 v1 = __ldg(hp + 1);
        float4 v2 = __ldg(hp + 2);
        float4 v3 = __ldg(hp + 3);
        red_add_v4(tp + 0,  v0.x, v0.y, v0.z, v0.w);
        red_add_v4(tp + 4,  v1.x, v1.y, v1.z, v1.w);
        red_add_v4(tp + 8,  v2.x, v2.y, v2.z, v2.w);
        red_add_v4(tp + 12, v3.x, v3.y, v3.z, v3.w);
    }
}

// Layer-1 epilogue: y = relu(d*t + b1); w = d*(y@M_g); self-term red to pool6
__global__ void k_post1(const float* __restrict__ b1p) {
    __shared__ float Ms[16][8];
    __shared__ float bs[16];
    __shared__ float bps[8];
    int g = blockIdx.x >= NBB ? 1 : 0;
    if (threadIdx.x < 128) ((float*)Ms)[threadIdx.x] = ((const float*)g_M[g])[threadIdx.x];
    if (threadIdx.x >= 128 && threadIdx.x < 144) bs[threadIdx.x - 128] = __ldg(b1p + threadIdx.x - 128);
    if (threadIdx.x >= 144 && threadIdx.x < 152) bps[threadIdx.x - 144] = g_b2P[g][threadIdx.x - 144];
    __syncthreads();
    int i = (blockIdx.x - g * NBB) * blockDim.x + threadIdx.x;
    if (i >= NN) return;
    float2 r = g_rec[g][i];
    float d = r.x;
    int bt = __float_as_int(r.y);
    const float4* tp = g_t[g] + (size_t)i * 4;
    float y[16];
#pragma unroll
    for (int c = 0; c < 4; c++) {
        float4 t = tp[c];
        y[4*c+0] = fmaxf(d * t.x + bs[4*c+0], 0.f);
        y[4*c+1] = fmaxf(d * t.y + bs[4*c+1], 0.f);
        y[4*c+2] = fmaxf(d * t.z + bs[4*c+2], 0.f);
        y[4*c+3] = fmaxf(d * t.w + bs[4*c+3], 0.f);
    }
    float acc[6];
#pragma unroll
    for (int o = 0; o < 6; o++) acc[o] = 0.f;
#pragma unroll
    for (int k = 0; k < 16; k++) {
        float yk = y[k];
#pragma unroll
        for (int o = 0; o < 6; o++) acc[o] += yk * Ms[k][o];
    }
    float w0 = d * acc[0], w1 = d * acc[1], w2 = d * acc[2];
    float w3 = d * acc[3], w4 = d * acc[4], w5 = d * acc[5];
    float4* wp = g_w[g] + (size_t)i * 2;
    wp[0] = make_float4(w0, w1, w2, w3);
    wp[1] = make_float4(w4, w5, 0.f, 0.f);
    // self term: d*w + b2P
    int rep = threadIdx.x & (NREP - 1);
    float* pp = (float*)&g_pool6[((size_t)(g * NREP + rep) * NG + bt) * 2];
    red_add_v4(pp, d * w0 + bps[0], d * w1 + bps[1], d * w2 + bps[2], d * w3 + bps[3]);
    red_add_v2(pp + 4, d * w4 + bps[4], d * w5 + bps[5]);
}

// Layer-2 edge pass (projected): pool6[batch[dst]] += dis[dst] * w[src]
__global__ void k_edge2(const int* __restrict__ ei0, const int* __restrict__ ei1) {
    int g = blockIdx.x >= NB_EDGE2 ? 1 : 0;
    const int* ei = g ? ei1 : ei0;
    int i = (blockIdx.x - g * NB_EDGE2) * blockDim.x + threadIdx.x;
    int2 s = __ldg((const int2*)ei + i);
    int2 dd = __ldg((const int2*)(ei + NE) + i);
    int rep = threadIdx.x & (NREP - 1);
    const float2* rec = g_rec[g];
    const float4* w = g_w[g];
#pragma unroll
    for (int k = 0; k < 2; k++) {
        int sv = k ? s.y : s.x;
        int dv = k ? dd.y : dd.x;
        float2 r = __ldg(rec + dv);
        float dis = r.x;
        int bt = __float_as_int(r.y);
        float4 wa = __ldg(w + (size_t)sv * 2);
        float2 wb = __ldg((const float2*)(w + (size_t)sv * 2 + 1));
        float* pp = (float*)&g_pool6[((size_t)(g * NREP + rep) * NG + bt) * 2];
        red_add_v4(pp, dis * wa.x, dis * wa.y, dis * wa.z, dis * wa.w);
        red_add_v2(pp + 4, dis * wb.x, dis * wb.y);
    }
}

// Sum replicas, divide by counts, add fcb; out = [1024,3] then [1024,3]
__global__ void k_final(const float* __restrict__ fcb, float* __restrict__ out) {
    int b = blockIdx.x * blockDim.x + threadIdx.x;
    if (b >= NG) return;
    float s[2][6];
#pragma unroll
    for (int g = 0; g < 2; g++) {
#pragma unroll
        for (int o = 0; o < 6; o++) s[g][o] = 0.f;
        for (int rp = 0; rp < NREP; rp++) {
            const float4* pp = &g_pool6[((size_t)(g * NREP + rp) * NG + b) * 2];
            float4 a = pp[0];
            float4 c = pp[1];
            s[g][0] += a.x; s[g][1] += a.y; s[g][2] += a.z; s[g][3] += a.w;
            s[g][4] += c.x; s[g][5] += c.y;
        }
    }
    float inv_r = 1.0f / fmaxf(g_cnt[b], 1.0f);
    float inv_l = 1.0f / fmaxf(g_cnt[NG + b], 1.0f);
#pragma unroll
    for (int o = 0; o < 6; o++) {
        float v = s[0][o] * inv_r + s[1][o] * inv_l + __ldg(fcb + o);
        if (o < 3) out[b * 3 + o] = v;
        else       out[NG * 3 + b * 3 + (o - 3)] = v;
    }
}

extern "C" void kernel_launch(void* const* d_in, const int* in_sizes, int n_in,
                              void* d_out, int out_size) {
    const float* emb = (const float*)d_in[0];
    const float* W1  = (const float*)d_in[1];
    const float* b1  = (const float*)d_in[2];
    const float* W2  = (const float*)d_in[3];
    const float* b2  = (const float*)d_in[4];
    const float* fcW = (const float*)d_in[5];
    const float* fcb = (const float*)d_in[6];
    const int* ids0  = (const int*)d_in[7];
    const int* ei0   = (const int*)d_in[8];
    const int* b0    = (const int*)d_in[9];
    const int* ids1  = (const int*)d_in[10];
    const int* ei1   = (const int*)d_in[11];
    const int* b1i   = (const int*)d_in[12];
    float* out = (float*)d_out;

    k_tab  <<<(NEMB + TPB - 1) / TPB, TPB>>>(emb, W1);
    k_mat  <<<1, TPB>>>(W2, b2, fcW);
    k_zero <<<(NN + TPB - 1) / TPB, TPB>>>();
    k_count<<<2 * NB_EDGE2, TPB>>>(ei0, ei1);
    k_embed<<<2 * NBB, TPB>>>(ids0, ids1, b0, b1i);
    k_edge1<<<2 * NB_EDGE2, TPB>>>(ei0, ei1);
    k_post1<<<2 * NBB, TPB>>>(b1);
    k_edge2<<<2 * NB_EDGE2, TPB>>>(ei0, ei1);
    k_final<<<(NG + TPB - 1) / TPB, TPB>>>(fcb, out);
}

// round 6
// speedup vs baseline: 1.6517x; 1.1657x over previous
#include <cuda_runtime.h>
#include <cuda_fp16.h>

#define NN 200000
#define NE 6400000
#define NG 1024
#define NEMB 1032
#define TPB 256
#define NREP 16
#define NBB ((NN + TPB - 1) / TPB)           // 782
#define NB_EDGE2 ((NE / 2 + TPB - 1) / TPB)  // 12500 (2 edges/thread, exact)

// Scratch (device globals; allocation-free)
__device__ float4 g_t[2][NN * 4];        // layer-1 accumulators (preloaded with self term)
__device__ uint4  g_hsh[2][NN * 2];      // hs1 packed f16: 16 halves = 32B/node
__device__ float2 g_rec[2][NN];          // {dis, batch bits}
__device__ uint4  g_wh[2][NN];           // w packed f16: 6 halves in 16B slot
__device__ int    g_deg[2][NN];          // in-degree
__device__ float4 g_tab[NEMB * 4];       // emb @ W1 (66KB, L1-hot)
__device__ float4 g_pool6[2 * NREP * NG * 2];  // [g][rep][graph][8 floats]
__device__ float  g_cnt[2 * NG];
__device__ float  g_M[2][16][8];         // M_g = W2 @ P_g^T  (16x6, padded)
__device__ float  g_b2P[2][8];           // b2 @ P_g^T

__device__ __forceinline__ unsigned h2u(__half2 h) {
    return *reinterpret_cast<unsigned*>(&h);
}
__device__ __forceinline__ __half2 u2h(unsigned u) {
    return *reinterpret_cast<__half2*>(&u);
}

__device__ __forceinline__ void red_add_v4(float* addr, float a, float b, float c, float d) {
    asm volatile("red.global.add.v4.f32 [%0], {%1,%2,%3,%4};"
                 :: "l"(addr), "f"(a), "f"(b), "f"(c), "f"(d) : "memory");
}
__device__ __forceinline__ void red_add_v2(float* addr, float a, float b) {
    asm volatile("red.global.add.v2.f32 [%0], {%1,%2};"
                 :: "l"(addr), "f"(a), "f"(b) : "memory");
}

// tab = emb @ W1
__global__ void k_tab(const float* __restrict__ emb, const float* __restrict__ W1) {
    __shared__ float Ws[256];
    if (threadIdx.x < 256) Ws[threadIdx.x] = W1[threadIdx.x];
    __syncthreads();
    int r = blockIdx.x * blockDim.x + threadIdx.x;
    if (r >= NEMB) return;
    const float* x = emb + r * 16;
    float acc[16];
#pragma unroll
    for (int j = 0; j < 16; j++) acc[j] = 0.f;
#pragma unroll
    for (int k = 0; k < 16; k++) {
        float xk = __ldg(x + k);
#pragma unroll
        for (int j = 0; j < 16; j++) acc[j] += xk * Ws[k * 16 + j];
    }
    float4* o = g_tab + r * 4;
#pragma unroll
    for (int c = 0; c < 4; c++)
        o[c] = make_float4(acc[4*c], acc[4*c+1], acc[4*c+2], acc[4*c+3]);
}

// M_g = W2 @ P_g^T ; b2P_g = b2 @ P_g^T   (P_g[o][j] = fcW[o*32 + 16g + j])
__global__ void k_mat(const float* __restrict__ W2, const float* __restrict__ b2,
                      const float* __restrict__ fcW) {
    int t = threadIdx.x;
    if (t < 192) {
        int g = t / 96, r = t % 96, k = r / 6, o = r % 6;
        float s = 0.f;
#pragma unroll
        for (int j = 0; j < 16; j++) s += __ldg(W2 + k * 16 + j) * __ldg(fcW + o * 32 + 16 * g + j);
        g_M[g][k][o] = s;
    } else if (t < 204) {
        int g = (t - 192) / 6, o = (t - 192) % 6;
        float s = 0.f;
#pragma unroll
        for (int j = 0; j < 16; j++) s += __ldg(b2 + j) * __ldg(fcW + o * 32 + 16 * g + j);
        g_b2P[g][o] = s;
    }
}

// Zero deg, pool6, cnt
__global__ void k_zero() {
    int i = blockIdx.x * blockDim.x + threadIdx.x;
    if (i < NN) { g_deg[0][i] = 0; g_deg[1][i] = 0; }
    if (i < 2 * NREP * NG * 2) g_pool6[i] = make_float4(0.f, 0.f, 0.f, 0.f);
    if (i < 2 * NG) g_cnt[i] = 0.f;
}

// In-degree count, both graphs, 2 edges/thread
__global__ void k_count(const int* __restrict__ ei0, const int* __restrict__ ei1) {
    int g = blockIdx.x >= NB_EDGE2 ? 1 : 0;
    const int* dst = (g ? ei1 : ei0) + NE;
    int i = (blockIdx.x - g * NB_EDGE2) * blockDim.x + threadIdx.x;
    int2 d = __ldg((const int2*)dst + i);
    atomicAdd(&g_deg[g][d.x], 1);
    atomicAdd(&g_deg[g][d.y], 1);
}

// dis; hs1 = tab[id]*dis -> f16 pack (gather src) AND f32 preload of g_t (self term);
// rec = {dis, batch}; per-graph counts
__global__ void k_embed(const int* __restrict__ ids0, const int* __restrict__ ids1,
                        const int* __restrict__ b0, const int* __restrict__ b1) {
    int g = blockIdx.x >= NBB ? 1 : 0;
    int i = (blockIdx.x - g * NBB) * blockDim.x + threadIdx.x;
    if (i >= NN) return;
    float d = rsqrtf((float)g_deg[g][i] + 1.0f);
    int id = __ldg((g ? ids1 : ids0) + i);
    int bt = __ldg((g ? b1 : b0) + i);
    float2 r; r.x = d; r.y = __int_as_float(bt);
    g_rec[g][i] = r;
    const float4* tb = g_tab + (size_t)id * 4;
    float4* tp = g_t[g] + (size_t)i * 4;
    __half2 hh[8];
#pragma unroll
    for (int c = 0; c < 4; c++) {
        float4 v = __ldg(tb + c);
        float4 hv = make_float4(v.x * d, v.y * d, v.z * d, v.w * d);
        tp[c] = hv;
        hh[2*c]   = __float22half2_rn(make_float2(hv.x, hv.y));
        hh[2*c+1] = __float22half2_rn(make_float2(hv.z, hv.w));
    }
    uint4* hp = g_hsh[g] + (size_t)i * 2;
    hp[0] = make_uint4(h2u(hh[0]), h2u(hh[1]), h2u(hh[2]), h2u(hh[3]));
    hp[1] = make_uint4(h2u(hh[4]), h2u(hh[5]), h2u(hh[6]), h2u(hh[7]));
    atomicAdd(&g_cnt[g * NG + bt], 1.0f);
}

// Layer-1 edge pass: t[dst] += hs1[src] (f16 gather, f32 v4 reds)
__global__ void k_edge1(const int* __restrict__ ei0, const int* __restrict__ ei1) {
    int g = blockIdx.x >= NB_EDGE2 ? 1 : 0;
    const int* ei = g ? ei1 : ei0;
    int i = (blockIdx.x - g * NB_EDGE2) * blockDim.x + threadIdx.x;
    int2 s = __ldg((const int2*)ei + i);
    int2 d = __ldg((const int2*)(ei + NE) + i);
    const uint4* hs = g_hsh[g];
    float4* t = g_t[g];
#pragma unroll
    for (int k = 0; k < 2; k++) {
        int sv = k ? s.y : s.x;
        int dv = k ? d.y : d.x;
        uint4 a = __ldg(hs + (size_t)sv * 2);
        uint4 b = __ldg(hs + (size_t)sv * 2 + 1);
        float* tp = (float*)(t + (size_t)dv * 4);
        float2 f0 = __half22float2(u2h(a.x));
        float2 f1 = __half22float2(u2h(a.y));
        float2 f2 = __half22float2(u2h(a.z));
        float2 f3 = __half22float2(u2h(a.w));
        float2 f4 = __half22float2(u2h(b.x));
        float2 f5 = __half22float2(u2h(b.y));
        float2 f6 = __half22float2(u2h(b.z));
        float2 f7 = __half22float2(u2h(b.w));
        red_add_v4(tp + 0,  f0.x, f0.y, f1.x, f1.y);
        red_add_v4(tp + 4,  f2.x, f2.y, f3.x, f3.y);
        red_add_v4(tp + 8,  f4.x, f4.y, f5.x, f5.y);
        red_add_v4(tp + 12, f6.x, f6.y, f7.x, f7.y);
    }
}

// Layer-1 epilogue: y = relu(d*t + b1); w = d*(y@M_g) -> f16 pack; self-term red
__global__ void k_post1(const float* __restrict__ b1p) {
    __shared__ float Ms[16][8];
    __shared__ float bs[16];
    __shared__ float bps[8];
    int g = blockIdx.x >= NBB ? 1 : 0;
    if (threadIdx.x < 128) ((float*)Ms)[threadIdx.x] = ((const float*)g_M[g])[threadIdx.x];
    if (threadIdx.x >= 128 && threadIdx.x < 144) bs[threadIdx.x - 128] = __ldg(b1p + threadIdx.x - 128);
    if (threadIdx.x >= 144 && threadIdx.x < 152) bps[threadIdx.x - 144] = g_b2P[g][threadIdx.x - 144];
    __syncthreads();
    int i = (blockIdx.x - g * NBB) * blockDim.x + threadIdx.x;
    if (i >= NN) return;
    float2 r = g_rec[g][i];
    float d = r.x;
    int bt = __float_as_int(r.y);
    const float4* tp = g_t[g] + (size_t)i * 4;
    float y[16];
#pragma unroll
    for (int c = 0; c < 4; c++) {
        float4 t = tp[c];
        y[4*c+0] = fmaxf(d * t.x + bs[4*c+0], 0.f);
        y[4*c+1] = fmaxf(d * t.y + bs[4*c+1], 0.f);
        y[4*c+2] = fmaxf(d * t.z + bs[4*c+2], 0.f);
        y[4*c+3] = fmaxf(d * t.w + bs[4*c+3], 0.f);
    }
    float acc[6];
#pragma unroll
    for (int o = 0; o < 6; o++) acc[o] = 0.f;
#pragma unroll
    for (int k = 0; k < 16; k++) {
        float yk = y[k];
#pragma unroll
        for (int o = 0; o < 6; o++) acc[o] += yk * Ms[k][o];
    }
    float w0 = d * acc[0], w1 = d * acc[1], w2 = d * acc[2];
    float w3 = d * acc[3], w4 = d * acc[4], w5 = d * acc[5];
    __half2 p0 = __float22half2_rn(make_float2(w0, w1));
    __half2 p1 = __float22half2_rn(make_float2(w2, w3));
    __half2 p2 = __float22half2_rn(make_float2(w4, w5));
    g_wh[g][i] = make_uint4(h2u(p0), h2u(p1), h2u(p2), 0u);
    // self term: d*w + b2P
    int rep = threadIdx.x & (NREP - 1);
    float* pp = (float*)&g_pool6[((size_t)(g * NREP + rep) * NG + bt) * 2];
    red_add_v4(pp, d * w0 + bps[0], d * w1 + bps[1], d * w2 + bps[2], d * w3 + bps[3]);
    red_add_v2(pp + 4, d * w4 + bps[4], d * w5 + bps[5]);
}

// Layer-2 edge pass (projected): pool6[batch[dst]] += dis[dst] * w[src]
__global__ void k_edge2(const int* __restrict__ ei0, const int* __restrict__ ei1) {
    int g = blockIdx.x >= NB_EDGE2 ? 1 : 0;
    const int* ei = g ? ei1 : ei0;
    int i = (blockIdx.x - g * NB_EDGE2) * blockDim.x + threadIdx.x;
    int2 s = __ldg((const int2*)ei + i);
    int2 dd = __ldg((const int2*)(ei + NE) + i);
    int rep = threadIdx.x & (NREP - 1);
    const float2* rec = g_rec[g];
    const uint4* w = g_wh[g];
#pragma unroll
    for (int k = 0; k < 2; k++) {
        int sv = k ? s.y : s.x;
        int dv = k ? dd.y : dd.x;
        float2 r = __ldg(rec + dv);
        float dis = r.x;
        int bt = __float_as_int(r.y);
        uint4 wp = __ldg(w + sv);
        float2 f0 = __half22float2(u2h(wp.x));
        float2 f1 = __half22float2(u2h(wp.y));
        float2 f2 = __half22float2(u2h(wp.z));
        float* pp = (float*)&g_pool6[((size_t)(g * NREP + rep) * NG + bt) * 2];
        red_add_v4(pp, dis * f0.x, dis * f0.y, dis * f1.x, dis * f1.y);
        red_add_v2(pp + 4, dis * f2.x, dis * f2.y);
    }
}

// Sum replicas, divide by counts, add fcb; out = [1024,3] then [1024,3]
__global__ void k_final(const float* __restrict__ fcb, float* __restrict__ out) {
    int b = blockIdx.x * blockDim.x + threadIdx.x;
    if (b >= NG) return;
    float s[2][6];
#pragma unroll
    for (int g = 0; g < 2; g++) {
#pragma unroll
        for (int o = 0; o < 6; o++) s[g][o] = 0.f;
        for (int rp = 0; rp < NREP; rp++) {
            const float4* pp = &g_pool6[((size_t)(g * NREP + rp) * NG + b) * 2];
            float4 a = pp[0];
            float4 c = pp[1];
            s[g][0] += a.x; s[g][1] += a.y; s[g][2] += a.z; s[g][3] += a.w;
            s[g][4] += c.x; s[g][5] += c.y;
        }
    }
    float inv_r = 1.0f / fmaxf(g_cnt[b], 1.0f);
    float inv_l = 1.0f / fmaxf(g_cnt[NG + b], 1.0f);
#pragma unroll
    for (int o = 0; o < 6; o++) {
        float v = s[0][o] * inv_r + s[1][o] * inv_l + __ldg(fcb + o);
        if (o < 3) out[b * 3 + o] = v;
        else       out[NG * 3 + b * 3 + (o - 3)] = v;
    }
}

extern "C" void kernel_launch(void* const* d_in, const int* in_sizes, int n_in,
                              void* d_out, int out_size) {
    const float* emb = (const float*)d_in[0];
    const float* W1  = (const float*)d_in[1];
    const float* b1  = (const float*)d_in[2];
    const float* W2  = (const float*)d_in[3];
    const float* b2  = (const float*)d_in[4];
    const float* fcW = (const float*)d_in[5];
    const float* fcb = (const float*)d_in[6];
    const int* ids0  = (const int*)d_in[7];
    const int* ei0   = (const int*)d_in[8];
    const int* b0    = (const int*)d_in[9];
    const int* ids1  = (const int*)d_in[10];
    const int* ei1   = (const int*)d_in[11];
    const int* b1i   = (const int*)d_in[12];
    float* out = (float*)d_out;

    k_tab  <<<(NEMB + TPB - 1) / TPB, TPB>>>(emb, W1);
    k_mat  <<<1, TPB>>>(W2, b2, fcW);
    k_zero <<<(NN + TPB - 1) / TPB, TPB>>>();
    k_count<<<2 * NB_EDGE2, TPB>>>(ei0, ei1);
    k_embed<<<2 * NBB, TPB>>>(ids0, ids1, b0, b1i);
    k_edge1<<<2 * NB_EDGE2, TPB>>>(ei0, ei1);
    k_post1<<<2 * NBB, TPB>>>(b1);
    k_edge2<<<2 * NB_EDGE2, TPB>>>(ei0, ei1);
    k_final<<<(NG + TPB - 1) / TPB, TPB>>>(fcb, out);
}

// round 7
// speedup vs baseline: 1.9869x; 1.2029x over previous
#include <cuda_runtime.h>
#include <cuda_fp16.h>

#define NN 200000
#define NE 6400000
#define NG 1024
#define NEMB 1032
#define TPB 256
#define NREP 16
#define NBB ((NN + TPB - 1) / TPB)           // 782
#define NB_EDGE2 ((NE / 2 + TPB - 1) / TPB)  // 12500 (2 edges/thread, exact)

// Scratch (device globals; allocation-free)
__device__ uint4  g_th[2][NN * 2];       // layer-1 accumulators, f16x2 packed (32B/node)
__device__ uint4  g_hsh[2][NN * 2];      // hs1 packed f16: 16 halves = 32B/node
__device__ float2 g_rec[2][NN];          // {dis, batch bits}
__device__ uint4  g_wh[2][NN];           // w packed f16: 6 halves in 16B slot
__device__ int    g_deg[2][NN];          // in-degree
__device__ float4 g_tab[NEMB * 4];       // emb @ W1 (66KB, L1-hot)
__device__ float4 g_pool6[2 * NREP * NG * 2];  // [g][rep][graph][8 floats]
__device__ float  g_cnt[2 * NG];
__device__ float  g_M[2][16][8];         // M_g = W2 @ P_g^T  (16x6, padded)
__device__ float  g_b2P[2][8];           // b2 @ P_g^T

__device__ __forceinline__ unsigned h2u(__half2 h) {
    return *reinterpret_cast<unsigned*>(&h);
}
__device__ __forceinline__ __half2 u2h(unsigned u) {
    return *reinterpret_cast<__half2*>(&u);
}

__device__ __forceinline__ void red_add_v4(float* addr, float a, float b, float c, float d) {
    asm volatile("red.global.add.v4.f32 [%0], {%1,%2,%3,%4};"
                 :: "l"(addr), "f"(a), "f"(b), "f"(c), "f"(d) : "memory");
}
__device__ __forceinline__ void red_add_v2(float* addr, float a, float b) {
    asm volatile("red.global.add.v2.f32 [%0], {%1,%2};"
                 :: "l"(addr), "f"(a), "f"(b) : "memory");
}
// packed vector f16x2 reduction: 8 halves in one op
__device__ __forceinline__ void red_add_v4h2(uint4* addr, uint4 v) {
    asm volatile("red.global.add.noftz.v4.f16x2 [%0], {%1,%2,%3,%4};"
                 :: "l"(addr), "r"(v.x), "r"(v.y), "r"(v.z), "r"(v.w) : "memory");
}

// tab = emb @ W1
__global__ void k_tab(const float* __restrict__ emb, const float* __restrict__ W1) {
    __shared__ float Ws[256];
    if (threadIdx.x < 256) Ws[threadIdx.x] = W1[threadIdx.x];
    __syncthreads();
    int r = blockIdx.x * blockDim.x + threadIdx.x;
    if (r >= NEMB) return;
    const float* x = emb + r * 16;
    float acc[16];
#pragma unroll
    for (int j = 0; j < 16; j++) acc[j] = 0.f;
#pragma unroll
    for (int k = 0; k < 16; k++) {
        float xk = __ldg(x + k);
#pragma unroll
        for (int j = 0; j < 16; j++) acc[j] += xk * Ws[k * 16 + j];
    }
    float4* o = g_tab + r * 4;
#pragma unroll
    for (int c = 0; c < 4; c++)
        o[c] = make_float4(acc[4*c], acc[4*c+1], acc[4*c+2], acc[4*c+3]);
}

// M_g = W2 @ P_g^T ; b2P_g = b2 @ P_g^T   (P_g[o][j] = fcW[o*32 + 16g + j])
__global__ void k_mat(const float* __restrict__ W2, const float* __restrict__ b2,
                      const float* __restrict__ fcW) {
    int t = threadIdx.x;
    if (t < 192) {
        int g = t / 96, r = t % 96, k = r / 6, o = r % 6;
        float s = 0.f;
#pragma unroll
        for (int j = 0; j < 16; j++) s += __ldg(W2 + k * 16 + j) * __ldg(fcW + o * 32 + 16 * g + j);
        g_M[g][k][o] = s;
    } else if (t < 204) {
        int g = (t - 192) / 6, o = (t - 192) % 6;
        float s = 0.f;
#pragma unroll
        for (int j = 0; j < 16; j++) s += __ldg(b2 + j) * __ldg(fcW + o * 32 + 16 * g + j);
        g_b2P[g][o] = s;
    }
}

// Zero deg, pool6, cnt
__global__ void k_zero() {
    int i = blockIdx.x * blockDim.x + threadIdx.x;
    if (i < NN) { g_deg[0][i] = 0; g_deg[1][i] = 0; }
    if (i < 2 * NREP * NG * 2) g_pool6[i] = make_float4(0.f, 0.f, 0.f, 0.f);
    if (i < 2 * NG) g_cnt[i] = 0.f;
}

// In-degree count, both graphs, 2 edges/thread
__global__ void k_count(const int* __restrict__ ei0, const int* __restrict__ ei1) {
    int g = blockIdx.x >= NB_EDGE2 ? 1 : 0;
    const int* dst = (g ? ei1 : ei0) + NE;
    int i = (blockIdx.x - g * NB_EDGE2) * blockDim.x + threadIdx.x;
    int2 d = __ldg((const int2*)dst + i);
    atomicAdd(&g_deg[g][d.x], 1);
    atomicAdd(&g_deg[g][d.y], 1);
}

// dis; hs1 = tab[id]*dis -> f16 pack, written to BOTH g_hsh (gather src) and
// g_th (f16 accumulator preload = self term); rec = {dis, batch}; counts
__global__ void k_embed(const int* __restrict__ ids0, const int* __restrict__ ids1,
                        const int* __restrict__ b0, const int* __restrict__ b1) {
    int g = blockIdx.x >= NBB ? 1 : 0;
    int i = (blockIdx.x - g * NBB) * blockDim.x + threadIdx.x;
    if (i >= NN) return;
    float d = rsqrtf((float)g_deg[g][i] + 1.0f);
    int id = __ldg((g ? ids1 : ids0) + i);
    int bt = __ldg((g ? b1 : b0) + i);
    float2 r; r.x = d; r.y = __int_as_float(bt);
    g_rec[g][i] = r;
    const float4* tb = g_tab + (size_t)id * 4;
    __half2 hh[8];
#pragma unroll
    for (int c = 0; c < 4; c++) {
        float4 v = __ldg(tb + c);
        hh[2*c]   = __float22half2_rn(make_float2(v.x * d, v.y * d));
        hh[2*c+1] = __float22half2_rn(make_float2(v.z * d, v.w * d));
    }
    uint4 a = make_uint4(h2u(hh[0]), h2u(hh[1]), h2u(hh[2]), h2u(hh[3]));
    uint4 b = make_uint4(h2u(hh[4]), h2u(hh[5]), h2u(hh[6]), h2u(hh[7]));
    uint4* hp = g_hsh[g] + (size_t)i * 2;
    hp[0] = a; hp[1] = b;
    uint4* tp = g_th[g] + (size_t)i * 2;
    tp[0] = a; tp[1] = b;
    atomicAdd(&g_cnt[g * NG + bt], 1.0f);
}

// Layer-1 edge pass: t[dst] += hs1[src] — pure gather + 2 packed f16x2 reds
__global__ void k_edge1(const int* __restrict__ ei0, const int* __restrict__ ei1) {
    int g = blockIdx.x >= NB_EDGE2 ? 1 : 0;
    const int* ei = g ? ei1 : ei0;
    int i = (blockIdx.x - g * NB_EDGE2) * blockDim.x + threadIdx.x;
    int2 s = __ldg((const int2*)ei + i);
    int2 d = __ldg((const int2*)(ei + NE) + i);
    const uint4* hs = g_hsh[g];
    uint4* t = g_th[g];
#pragma unroll
    for (int k = 0; k < 2; k++) {
        int sv = k ? s.y : s.x;
        int dv = k ? d.y : d.x;
        uint4 a = __ldg(hs + (size_t)sv * 2);
        uint4 b = __ldg(hs + (size_t)sv * 2 + 1);
        uint4* tp = t + (size_t)dv * 2;
        red_add_v4h2(tp, a);
        red_add_v4h2(tp + 1, b);
    }
}

// Layer-1 epilogue: y = relu(d*t + b1); w = d*(y@M_g) -> f16 pack; self-term red
__global__ void k_post1(const float* __restrict__ b1p) {
    __shared__ float Ms[16][8];
    __shared__ float bs[16];
    __shared__ float bps[8];
    int g = blockIdx.x >= NBB ? 1 : 0;
    if (threadIdx.x < 128) ((float*)Ms)[threadIdx.x] = ((const float*)g_M[g])[threadIdx.x];
    if (threadIdx.x >= 128 && threadIdx.x < 144) bs[threadIdx.x - 128] = __ldg(b1p + threadIdx.x - 128);
    if (threadIdx.x >= 144 && threadIdx.x < 152) bps[threadIdx.x - 144] = g_b2P[g][threadIdx.x - 144];
    __syncthreads();
    int i = (blockIdx.x - g * NBB) * blockDim.x + threadIdx.x;
    if (i >= NN) return;
    float2 r = g_rec[g][i];
    float d = r.x;
    int bt = __float_as_int(r.y);
    const uint4* tp = g_th[g] + (size_t)i * 2;
    uint4 ta = tp[0];
    uint4 tb = tp[1];
    float y[16];
    {
        unsigned u[8] = {ta.x, ta.y, ta.z, ta.w, tb.x, tb.y, tb.z, tb.w};
#pragma unroll
        for (int c = 0; c < 8; c++) {
            float2 f = __half22float2(u2h(u[c]));
            y[2*c+0] = fmaxf(d * f.x + bs[2*c+0], 0.f);
            y[2*c+1] = fmaxf(d * f.y + bs[2*c+1], 0.f);
        }
    }
    float acc[6];
#pragma unroll
    for (int o = 0; o < 6; o++) acc[o] = 0.f;
#pragma unroll
    for (int k = 0; k < 16; k++) {
        float yk = y[k];
#pragma unroll
        for (int o = 0; o < 6; o++) acc[o] += yk * Ms[k][o];
    }
    float w0 = d * acc[0], w1 = d * acc[1], w2 = d * acc[2];
    float w3 = d * acc[3], w4 = d * acc[4], w5 = d * acc[5];
    __half2 p0 = __float22half2_rn(make_float2(w0, w1));
    __half2 p1 = __float22half2_rn(make_float2(w2, w3));
    __half2 p2 = __float22half2_rn(make_float2(w4, w5));
    g_wh[g][i] = make_uint4(h2u(p0), h2u(p1), h2u(p2), 0u);
    // self term: d*w + b2P
    int rep = threadIdx.x & (NREP - 1);
    float* pp = (float*)&g_pool6[((size_t)(g * NREP + rep) * NG + bt) * 2];
    red_add_v4(pp, d * w0 + bps[0], d * w1 + bps[1], d * w2 + bps[2], d * w3 + bps[3]);
    red_add_v2(pp + 4, d * w4 + bps[4], d * w5 + bps[5]);
}

// Layer-2 edge pass (projected): pool6[batch[dst]] += dis[dst] * w[src]
__global__ void k_edge2(const int* __restrict__ ei0, const int* __restrict__ ei1) {
    int g = blockIdx.x >= NB_EDGE2 ? 1 : 0;
    const int* ei = g ? ei1 : ei0;
    int i = (blockIdx.x - g * NB_EDGE2) * blockDim.x + threadIdx.x;
    int2 s = __ldg((const int2*)ei + i);
    int2 dd = __ldg((const int2*)(ei + NE) + i);
    int rep = threadIdx.x & (NREP - 1);
    const float2* rec = g_rec[g];
    const uint4* w = g_wh[g];
#pragma unroll
    for (int k = 0; k < 2; k++) {
        int sv = k ? s.y : s.x;
        int dv = k ? dd.y : dd.x;
        float2 r = __ldg(rec + dv);
        float dis = r.x;
        int bt = __float_as_int(r.y);
        uint4 wp = __ldg(w + sv);
        float2 f0 = __half22float2(u2h(wp.x));
        float2 f1 = __half22float2(u2h(wp.y));
        float2 f2 = __half22float2(u2h(wp.z));
        float* pp = (float*)&g_pool6[((size_t)(g * NREP + rep) * NG + bt) * 2];
        red_add_v4(pp, dis * f0.x, dis * f0.y, dis * f1.x, dis * f1.y);
        red_add_v2(pp + 4, dis * f2.x, dis * f2.y);
    }
}

// Sum replicas, divide by counts, add fcb; out = [1024,3] then [1024,3]
__global__ void k_final(const float* __restrict__ fcb, float* __restrict__ out) {
    int b = blockIdx.x * blockDim.x + threadIdx.x;
    if (b >= NG) return;
    float s[2][6];
#pragma unroll
    for (int g = 0; g < 2; g++) {
#pragma unroll
        for (int o = 0; o < 6; o++) s[g][o] = 0.f;
        for (int rp = 0; rp < NREP; rp++) {
            const float4* pp = &g_pool6[((size_t)(g * NREP + rp) * NG + b) * 2];
            float4 a = pp[0];
            float4 c = pp[1];
            s[g][0] += a.x; s[g][1] += a.y; s[g][2] += a.z; s[g][3] += a.w;
            s[g][4] += c.x; s[g][5] += c.y;
        }
    }
    float inv_r = 1.0f / fmaxf(g_cnt[b], 1.0f);
    float inv_l = 1.0f / fmaxf(g_cnt[NG + b], 1.0f);
#pragma unroll
    for (int o = 0; o < 6; o++) {
        float v = s[0][o] * inv_r + s[1][o] * inv_l + __ldg(fcb + o);
        if (o < 3) out[b * 3 + o] = v;
        else       out[NG * 3 + b * 3 + (o - 3)] = v;
    }
}

extern "C" void kernel_launch(void* const* d_in, const int* in_sizes, int n_in,
                              void* d_out, int out_size) {
    const float* emb = (const float*)d_in[0];
    const float* W1  = (const float*)d_in[1];
    const float* b1  = (const float*)d_in[2];
    const float* W2  = (const float*)d_in[3];
    const float* b2  = (const float*)d_in[4];
    const float* fcW = (const float*)d_in[5];
    const float* fcb = (const float*)d_in[6];
    const int* ids0  = (const int*)d_in[7];
    const int* ei0   = (const int*)d_in[8];
    const int* b0    = (const int*)d_in[9];
    const int* ids1  = (const int*)d_in[10];
    const int* ei1   = (const int*)d_in[11];
    const int* b1i   = (const int*)d_in[12];
    float* out = (float*)d_out;

    k_tab  <<<(NEMB + TPB - 1) / TPB, TPB>>>(emb, W1);
    k_mat  <<<1, TPB>>>(W2, b2, fcW);
    k_zero <<<(NN + TPB - 1) / TPB, TPB>>>();
    k_count<<<2 * NB_EDGE2, TPB>>>(ei0, ei1);
    k_embed<<<2 * NBB, TPB>>>(ids0, ids1, b0, b1i);
    k_edge1<<<2 * NB_EDGE2, TPB>>>(ei0, ei1);
    k_post1<<<2 * NBB, TPB>>>(b1);
    k_edge2<<<2 * NB_EDGE2, TPB>>>(ei0, ei1);
    k_final<<<(NG + TPB - 1) / TPB, TPB>>>(fcb, out);
}

// round 8
// speedup vs baseline: 2.5163x; 1.2664x over previous
#include <cuda_runtime.h>
#include <cuda_fp16.h>

#define NN 200000
#define NE 6400000
#define NG 1024
#define NEMB 1032
#define TPB 256
#define NREP 16
#define NBB ((NN + TPB - 1) / TPB)           // 782
#define NB_EDGE2 ((NE / 2 + TPB - 1) / TPB)  // 12500 (2 edges/thread, exact)

// Scratch (device globals; allocation-free)
__device__ uint4  g_th[2][NN * 2];       // layer-1 accumulators, f16x2 packed (32B/node)
__device__ uint4  g_hsh[2][NN * 2];      // hs1 packed f16: 16 halves = 32B/node
__device__ float2 g_rec[2][NN];          // {dis, batch bits}
__device__ uint4  g_wh[2][NN];           // w packed f16: 6 halves in 16B slot
__device__ uint4  g_t6[2][NN];           // layer-2 accumulators (f16 x6+pad, preloaded w_i)
__device__ int    g_deg[2][NN];          // in-degree
__device__ float4 g_tab[NEMB * 4];       // emb @ W1 (66KB, L1-hot)
__device__ float4 g_pool6[2 * NREP * NG * 2];  // [g][rep][graph][8 floats]
__device__ float  g_cnt[2 * NG];
__device__ float  g_M[2][16][8];         // M_g = W2 @ P_g^T  (16x6, padded)
__device__ float  g_b2P[2][8];           // b2 @ P_g^T

__device__ __forceinline__ unsigned h2u(__half2 h) {
    return *reinterpret_cast<unsigned*>(&h);
}
__device__ __forceinline__ __half2 u2h(unsigned u) {
    return *reinterpret_cast<__half2*>(&u);
}

__device__ __forceinline__ void red_add_v4(float* addr, float a, float b, float c, float d) {
    asm volatile("red.global.add.v4.f32 [%0], {%1,%2,%3,%4};"
                 :: "l"(addr), "f"(a), "f"(b), "f"(c), "f"(d) : "memory");
}
__device__ __forceinline__ void red_add_v2(float* addr, float a, float b) {
    asm volatile("red.global.add.v2.f32 [%0], {%1,%2};"
                 :: "l"(addr), "f"(a), "f"(b) : "memory");
}
// packed vector f16x2 reduction: 8 halves in one op
__device__ __forceinline__ void red_add_v4h2(uint4* addr, uint4 v) {
    asm volatile("red.global.add.noftz.v4.f16x2 [%0], {%1,%2,%3,%4};"
                 :: "l"(addr), "r"(v.x), "r"(v.y), "r"(v.z), "r"(v.w) : "memory");
}

// tab = emb @ W1
__global__ void k_tab(const float* __restrict__ emb, const float* __restrict__ W1) {
    __shared__ float Ws[256];
    if (threadIdx.x < 256) Ws[threadIdx.x] = W1[threadIdx.x];
    __syncthreads();
    int r = blockIdx.x * blockDim.x + threadIdx.x;
    if (r >= NEMB) return;
    const float* x = emb + r * 16;
    float acc[16];
#pragma unroll
    for (int j = 0; j < 16; j++) acc[j] = 0.f;
#pragma unroll
    for (int k = 0; k < 16; k++) {
        float xk = __ldg(x + k);
#pragma unroll
        for (int j = 0; j < 16; j++) acc[j] += xk * Ws[k * 16 + j];
    }
    float4* o = g_tab + r * 4;
#pragma unroll
    for (int c = 0; c < 4; c++)
        o[c] = make_float4(acc[4*c], acc[4*c+1], acc[4*c+2], acc[4*c+3]);
}

// M_g = W2 @ P_g^T ; b2P_g = b2 @ P_g^T   (P_g[o][j] = fcW[o*32 + 16g + j])
__global__ void k_mat(const float* __restrict__ W2, const float* __restrict__ b2,
                      const float* __restrict__ fcW) {
    int t = threadIdx.x;
    if (t < 192) {
        int g = t / 96, r = t % 96, k = r / 6, o = r % 6;
        float s = 0.f;
#pragma unroll
        for (int j = 0; j < 16; j++) s += __ldg(W2 + k * 16 + j) * __ldg(fcW + o * 32 + 16 * g + j);
        g_M[g][k][o] = s;
    } else if (t < 204) {
        int g = (t - 192) / 6, o = (t - 192) % 6;
        float s = 0.f;
#pragma unroll
        for (int j = 0; j < 16; j++) s += __ldg(b2 + j) * __ldg(fcW + o * 32 + 16 * g + j);
        g_b2P[g][o] = s;
    }
}

// Zero deg, pool6, cnt
__global__ void k_zero() {
    int i = blockIdx.x * blockDim.x + threadIdx.x;
    if (i < NN) { g_deg[0][i] = 0; g_deg[1][i] = 0; }
    if (i < 2 * NREP * NG * 2) g_pool6[i] = make_float4(0.f, 0.f, 0.f, 0.f);
    if (i < 2 * NG) g_cnt[i] = 0.f;
}

// In-degree count, both graphs, 2 edges/thread
__global__ void k_count(const int* __restrict__ ei0, const int* __restrict__ ei1) {
    int g = blockIdx.x >= NB_EDGE2 ? 1 : 0;
    const int* dst = (g ? ei1 : ei0) + NE;
    int i = (blockIdx.x - g * NB_EDGE2) * blockDim.x + threadIdx.x;
    int2 d = __ldg((const int2*)dst + i);
    atomicAdd(&g_deg[g][d.x], 1);
    atomicAdd(&g_deg[g][d.y], 1);
}

// dis; hs1 = tab[id]*dis -> f16 pack, written to BOTH g_hsh (gather src) and
// g_th (f16 accumulator preload = self term); rec = {dis, batch}; counts
__global__ void k_embed(const int* __restrict__ ids0, const int* __restrict__ ids1,
                        const int* __restrict__ b0, const int* __restrict__ b1) {
    int g = blockIdx.x >= NBB ? 1 : 0;
    int i = (blockIdx.x - g * NBB) * blockDim.x + threadIdx.x;
    if (i >= NN) return;
    float d = rsqrtf((float)g_deg[g][i] + 1.0f);
    int id = __ldg((g ? ids1 : ids0) + i);
    int bt = __ldg((g ? b1 : b0) + i);
    float2 r; r.x = d; r.y = __int_as_float(bt);
    g_rec[g][i] = r;
    const float4* tb = g_tab + (size_t)id * 4;
    __half2 hh[8];
#pragma unroll
    for (int c = 0; c < 4; c++) {
        float4 v = __ldg(tb + c);
        hh[2*c]   = __float22half2_rn(make_float2(v.x * d, v.y * d));
        hh[2*c+1] = __float22half2_rn(make_float2(v.z * d, v.w * d));
    }
    uint4 a = make_uint4(h2u(hh[0]), h2u(hh[1]), h2u(hh[2]), h2u(hh[3]));
    uint4 b = make_uint4(h2u(hh[4]), h2u(hh[5]), h2u(hh[6]), h2u(hh[7]));
    uint4* hp = g_hsh[g] + (size_t)i * 2;
    hp[0] = a; hp[1] = b;
    uint4* tp = g_th[g] + (size_t)i * 2;
    tp[0] = a; tp[1] = b;
    atomicAdd(&g_cnt[g * NG + bt], 1.0f);
}

// Layer-1 edge pass: t[dst] += hs1[src] — pure gather + 2 packed f16x2 reds
__global__ void k_edge1(const int* __restrict__ ei0, const int* __restrict__ ei1) {
    int g = blockIdx.x >= NB_EDGE2 ? 1 : 0;
    const int* ei = g ? ei1 : ei0;
    int i = (blockIdx.x - g * NB_EDGE2) * blockDim.x + threadIdx.x;
    int2 s = __ldg((const int2*)ei + i);
    int2 d = __ldg((const int2*)(ei + NE) + i);
    const uint4* hs = g_hsh[g];
    uint4* t = g_th[g];
#pragma unroll
    for (int k = 0; k < 2; k++) {
        int sv = k ? s.y : s.x;
        int dv = k ? d.y : d.x;
        uint4 a = __ldg(hs + (size_t)sv * 2);
        uint4 b = __ldg(hs + (size_t)sv * 2 + 1);
        uint4* tp = t + (size_t)dv * 2;
        red_add_v4h2(tp, a);
        red_add_v4h2(tp + 1, b);
    }
}

// Layer-1 epilogue: y = relu(d*t + b1); w = d*(y@M_g) -> f16 pack into g_wh
// AND preload g_t6 with w (self term of layer 2)
__global__ void k_post1(const float* __restrict__ b1p) {
    __shared__ float Ms[16][8];
    __shared__ float bs[16];
    int g = blockIdx.x >= NBB ? 1 : 0;
    if (threadIdx.x < 128) ((float*)Ms)[threadIdx.x] = ((const float*)g_M[g])[threadIdx.x];
    if (threadIdx.x >= 128 && threadIdx.x < 144) bs[threadIdx.x - 128] = __ldg(b1p + threadIdx.x - 128);
    __syncthreads();
    int i = (blockIdx.x - g * NBB) * blockDim.x + threadIdx.x;
    if (i >= NN) return;
    float d = g_rec[g][i].x;
    const uint4* tp = g_th[g] + (size_t)i * 2;
    uint4 ta = tp[0];
    uint4 tb = tp[1];
    float y[16];
    {
        unsigned u[8] = {ta.x, ta.y, ta.z, ta.w, tb.x, tb.y, tb.z, tb.w};
#pragma unroll
        for (int c = 0; c < 8; c++) {
            float2 f = __half22float2(u2h(u[c]));
            y[2*c+0] = fmaxf(d * f.x + bs[2*c+0], 0.f);
            y[2*c+1] = fmaxf(d * f.y + bs[2*c+1], 0.f);
        }
    }
    float acc[6];
#pragma unroll
    for (int o = 0; o < 6; o++) acc[o] = 0.f;
#pragma unroll
    for (int k = 0; k < 16; k++) {
        float yk = y[k];
#pragma unroll
        for (int o = 0; o < 6; o++) acc[o] += yk * Ms[k][o];
    }
    __half2 p0 = __float22half2_rn(make_float2(d * acc[0], d * acc[1]));
    __half2 p1 = __float22half2_rn(make_float2(d * acc[2], d * acc[3]));
    __half2 p2 = __float22half2_rn(make_float2(d * acc[4], d * acc[5]));
    uint4 w = make_uint4(h2u(p0), h2u(p1), h2u(p2), 0u);
    g_wh[g][i] = w;
    g_t6[g][i] = w;   // self-term preload
}

// Layer-2 edge pass: t6[dst] += w[src]  (1 gather + 1 packed red per edge)
__global__ void k_edge2(const int* __restrict__ ei0, const int* __restrict__ ei1) {
    int g = blockIdx.x >= NB_EDGE2 ? 1 : 0;
    const int* ei = g ? ei1 : ei0;
    int i = (blockIdx.x - g * NB_EDGE2) * blockDim.x + threadIdx.x;
    int2 s = __ldg((const int2*)ei + i);
    int2 dd = __ldg((const int2*)(ei + NE) + i);
    const uint4* w = g_wh[g];
    uint4* t6 = g_t6[g];
    uint4 w0 = __ldg(w + s.x);
    uint4 w1 = __ldg(w + s.y);
    red_add_v4h2(t6 + dd.x, w0);
    red_add_v4h2(t6 + dd.y, w1);
}

// Layer-2 epilogue: pool6[batch] += dis*t6 + b2P
__global__ void k_post2() {
    __shared__ float bps[8];
    int g = blockIdx.x >= NBB ? 1 : 0;
    if (threadIdx.x < 8) bps[threadIdx.x] = g_b2P[g][threadIdx.x];
    __syncthreads();
    int i = (blockIdx.x - g * NBB) * blockDim.x + threadIdx.x;
    if (i >= NN) return;
    float2 r = g_rec[g][i];
    float d = r.x;
    int bt = __float_as_int(r.y);
    uint4 t = g_t6[g][i];
    float2 f0 = __half22float2(u2h(t.x));
    float2 f1 = __half22float2(u2h(t.y));
    float2 f2 = __half22float2(u2h(t.z));
    int rep = threadIdx.x & (NREP - 1);
    float* pp = (float*)&g_pool6[((size_t)(g * NREP + rep) * NG + bt) * 2];
    red_add_v4(pp, d * f0.x + bps[0], d * f0.y + bps[1], d * f1.x + bps[2], d * f1.y + bps[3]);
    red_add_v2(pp + 4, d * f2.x + bps[4], d * f2.y + bps[5]);
}

// Sum replicas, divide by counts, add fcb; out = [1024,3] then [1024,3]
__global__ void k_final(const float* __restrict__ fcb, float* __restrict__ out) {
    int b = blockIdx.x * blockDim.x + threadIdx.x;
    if (b >= NG) return;
    float s[2][6];
#pragma unroll
    for (int g = 0; g < 2; g++) {
#pragma unroll
        for (int o = 0; o < 6; o++) s[g][o] = 0.f;
        for (int rp = 0; rp < NREP; rp++) {
            const float4* pp = &g_pool6[((size_t)(g * NREP + rp) * NG + b) * 2];
            float4 a = pp[0];
            float4 c = pp[1];
            s[g][0] += a.x; s[g][1] += a.y; s[g][2] += a.z; s[g][3] += a.w;
            s[g][4] += c.x; s[g][5] += c.y;
        }
    }
    float inv_r = 1.0f / fmaxf(g_cnt[b], 1.0f);
    float inv_l = 1.0f / fmaxf(g_cnt[NG + b], 1.0f);
#pragma unroll
    for (int o = 0; o < 6; o++) {
        float v = s[0][o] * inv_r + s[1][o] * inv_l + __ldg(fcb + o);
        if (o < 3) out[b * 3 + o] = v;
        else       out[NG * 3 + b * 3 + (o - 3)] = v;
    }
}

extern "C" void kernel_launch(void* const* d_in, const int* in_sizes, int n_in,
                              void* d_out, int out_size) {
    const float* emb = (const float*)d_in[0];
    const float* W1  = (const float*)d_in[1];
    const float* b1  = (const float*)d_in[2];
    const float* W2  = (const float*)d_in[3];
    const float* b2  = (const float*)d_in[4];
    const float* fcW = (const float*)d_in[5];
    const float* fcb = (const float*)d_in[6];
    const int* ids0  = (const int*)d_in[7];
    const int* ei0   = (const int*)d_in[8];
    const int* b0    = (const int*)d_in[9];
    const int* ids1  = (const int*)d_in[10];
    const int* ei1   = (const int*)d_in[11];
    const int* b1i   = (const int*)d_in[12];
    float* out = (float*)d_out;

    k_tab  <<<(NEMB + TPB - 1) / TPB, TPB>>>(emb, W1);
    k_mat  <<<1, TPB>>>(W2, b2, fcW);
    k_zero <<<(NN + TPB - 1) / TPB, TPB>>>();
    k_count<<<2 * NB_EDGE2, TPB>>>(ei0, ei1);
    k_embed<<<2 * NBB, TPB>>>(ids0, ids1, b0, b1i);
    k_edge1<<<2 * NB_EDGE2, TPB>>>(ei0, ei1);
    k_post1<<<2 * NBB, TPB>>>(b1);
    k_edge2<<<2 * NB_EDGE2, TPB>>>(ei0, ei1);
    k_post2<<<2 * NBB, TPB>>>();
    k_final<<<(NG + TPB - 1) / TPB, TPB>>>(fcb, out);
}